// round 12
// baseline (speedup 1.0000x reference)
#include <cuda_runtime.h>
#include <math.h>

#define NE   4096
#define EMB  64
#define NB   4
#define FCO  100
#define GRID 148
#define NTHR 512
#define NWARP 16
#define NWSLOT (GRID * NWARP)     // 2368 warp slots
#define NITEM 16384               // NB * 512 row-groups(8) * 8 j-eighths
#define TBL_FLOATS (5 * NE)       // q,q2,h0,h1,h2 = 80KB
#define RING_INTS (NWARP * 4 * 512)   // 16 warps x 4 slots x 2KB = 128KB
#define SMEM_BYTES (TBL_FLOATS * 4 + RING_INTS * 4)  // 208KB

// Scratch (allocation-free rule: __device__ globals)
__device__ float g_h0[NE], g_h1[NE], g_h2[NE];
__device__ float g_src[NE], g_dst[NE];
__device__ float g_x[NB * NE * 3];
__device__ float g_pS[8][NB * NE];
__device__ float g_pT0[8][NB * NE], g_pT1[8][NB * NE], g_pT2[8][NB * NE];
__device__ unsigned g_mbits = 0u;   // static init; atomicMax idempotent across replays
__device__ unsigned g_cnt = 0u;     // monotonic ticket barrier (no reset needed)

__device__ __forceinline__ unsigned enc_f(float f) {
    unsigned b = __float_as_uint(f);
    return (b & 0x80000000u) ? ~b : (b | 0x80000000u);
}
__device__ __forceinline__ float dec_f(unsigned u) {
    unsigned b = (u & 0x80000000u) ? (u & 0x7fffffffu) : ~u;
    return __uint_as_float(b);
}
__device__ __forceinline__ unsigned smem_u32(const void* p) {
    return (unsigned)__cvta_generic_to_shared(p);
}
__device__ __forceinline__ void cp16(unsigned dst, const void* src) {
    asm volatile("cp.async.cg.shared.global [%0], [%1], 16;" :: "r"(dst), "l"(src) : "memory");
}
__device__ __forceinline__ void cp_commit() {
    asm volatile("cp.async.commit_group;" ::: "memory");
}
__device__ __forceinline__ void cp_wait3() {
    asm volatile("cp.async.wait_group 3;" ::: "memory");
}
__device__ __forceinline__ void cp_wait0() {
    asm volatile("cp.async.wait_group 0;" ::: "memory");
}

// Grid-wide barrier: monotonic ticket epochs; all 148 CTAs resident (1 CTA/SM).
__device__ __forceinline__ void gsync() {
    __syncthreads();
    if (threadIdx.x == 0) {
        __threadfence();
        unsigned t = atomicAdd(&g_cnt, 1u);
        unsigned target = t - (t % (unsigned)GRID) + (unsigned)GRID;
        while ((int)(*(volatile unsigned*)&g_cnt - target) < 0)
            __nanosleep(64);
        __threadfence();
    }
    __syncthreads();
}

// Packed f32x2 helpers (sm_103a)
typedef unsigned long long ull;
__device__ __forceinline__ ull pack2(float lo, float hi) {
    ull r; asm("mov.b64 %0, {%1, %2};" : "=l"(r) : "f"(lo), "f"(hi)); return r;
}
__device__ __forceinline__ void unpack2(float& lo, float& hi, ull v) {
    asm("mov.b64 {%0, %1}, %2;" : "=f"(lo), "=f"(hi) : "l"(v));
}
__device__ __forceinline__ ull mul2(ull a, ull b) {
    ull d; asm("mul.rn.f32x2 %0, %1, %2;" : "=l"(d) : "l"(a), "l"(b)); return d;
}
#define FMA_X2(d, a, b, c) \
    asm("fma.rn.f32x2 %0, %1, %2, %3;" : "=l"(d) : "l"(a), "l"(b), "l"(c))
#define ADD_X2(d, a, b) \
    asm("add.rn.f32x2 %0, %1, %2;" : "=l"(d) : "l"(a), "l"(b))

// ---------------------------------------------------------------------------
// ONE persistent kernel: prep -> sync -> mainloop -> sync -> elu -> sync -> fc
// ---------------------------------------------------------------------------
__global__ void __launch_bounds__(NTHR, 1) k_all(
    const int*   __restrict__ adj,
    const float* __restrict__ emb,
    const float* __restrict__ W,
    const float* __restrict__ av,
    const float* __restrict__ fcw,
    const float* __restrict__ fcb,
    float*       __restrict__ out)
{
    extern __shared__ float sm[];
    float* sq  = sm;
    float* sq2 = sm + NE;
    float* sh0 = sm + 2 * NE;
    float* sh1 = sm + 3 * NE;
    float* sh2 = sm + 4 * NE;
    int*   ring = (int*)(sm + TBL_FLOATS);

    int tid = threadIdx.x, bid = blockIdx.x;
    int warp = tid >> 5, lane = tid & 31;

    // ---------------- Phase 0: prep (blocks 0-31, 16384 threads) ----------
    if (bid < 32) {
        int t = bid * NTHR + tid;
        int row = t >> 2, sub = t & 3;
        const float4* e4 = (const float4*)(emb + row * EMB);
        float h0 = 0.f, h1 = 0.f, h2 = 0.f;
#pragma unroll
        for (int i = 0; i < 4; i++) {
            int fi = sub + i * 4;
            float4 ev = __ldg(e4 + fi);
            int k = fi * 4;
            h0 = fmaf(ev.x, __ldg(W + (k+0)*3+0), h0); h1 = fmaf(ev.x, __ldg(W + (k+0)*3+1), h1); h2 = fmaf(ev.x, __ldg(W + (k+0)*3+2), h2);
            h0 = fmaf(ev.y, __ldg(W + (k+1)*3+0), h0); h1 = fmaf(ev.y, __ldg(W + (k+1)*3+1), h1); h2 = fmaf(ev.y, __ldg(W + (k+1)*3+2), h2);
            h0 = fmaf(ev.z, __ldg(W + (k+2)*3+0), h0); h1 = fmaf(ev.z, __ldg(W + (k+2)*3+1), h1); h2 = fmaf(ev.z, __ldg(W + (k+2)*3+2), h2);
            h0 = fmaf(ev.w, __ldg(W + (k+3)*3+0), h0); h1 = fmaf(ev.w, __ldg(W + (k+3)*3+1), h1); h2 = fmaf(ev.w, __ldg(W + (k+3)*3+2), h2);
        }
#pragma unroll
        for (int o = 1; o <= 2; o <<= 1) {
            h0 += __shfl_xor_sync(0xffffffffu, h0, o);
            h1 += __shfl_xor_sync(0xffffffffu, h1, o);
            h2 += __shfl_xor_sync(0xffffffffu, h2, o);
        }
        if (sub == 0) {
            g_h0[row] = h0; g_h1[row] = h1; g_h2[row] = h2;
            g_src[row] = h0 * __ldg(av + 0) + h1 * __ldg(av + 1) + h2 * __ldg(av + 2);
            float d    = h0 * __ldg(av + 3) + h1 * __ldg(av + 4) + h2 * __ldg(av + 5);
            g_dst[row] = d;
            atomicMax(&g_mbits, enc_f(d));
        }
    }
    gsync();

    // ---------------- Phase 1: main adj stream (all blocks) ----------------
    {
        int lsub = lane & 15, halfr0 = (lane >> 4) << 2;
        int wid = bid * NWARP + warp;

        float Md = dec_f(g_mbits);
        for (int i = tid; i < NE; i += NTHR) {
            float d = g_dst[i];
            sq[i]  = expf(d - Md);
            sq2[i] = expf(0.2f * (d - Md));
            sh0[i] = g_h0[i]; sh1[i] = g_h1[i]; sh2[i] = g_h2[i];
        }
        __syncthreads();

        int nItems = 0;
        for (int it = wid; it < NITEM; it += NWSLOT) nItems++;
        int total = nItems * 8;   // wid < 2368 < 16384 -> total >= 8 always

        int* wring = ring + warp * 2048;              // 4 slots x 512 ints
        int cp_row = lane >> 2, cp_col = (lane & 3) << 2;   // ints
        unsigned cp_dst0 = smem_u32(wring) + (unsigned)((cp_row << 6) + cp_col) * 4u;

        auto issue = [&](int step) {
            int it = wid + (step >> 3) * NWSLOT;
            int slot = step & 3;
            int b = it >> 12, grp = (it >> 3) & 511, je = it & 7;
            const int* src = adj
                + ((size_t)((b << 12) + (grp << 3) + cp_row)) * NE
                + (je << 9) + ((step & 7) << 6) + cp_col;
            unsigned dst = cp_dst0 + (unsigned)slot * 2048u;
#pragma unroll
            for (int k = 0; k < 4; k++)
                cp16(dst + k * 64u, src + k * 16);
            cp_commit();
        };

        for (int p = 0; p < 3 && p < total; p++) issue(p);

        ull Sp[4] = {0,0,0,0}, T0p[4] = {0,0,0,0}, T1p[4] = {0,0,0,0}, T2p[4] = {0,0,0,0};
        ull Ca2[4], Cb2[4];
        float W0s[4];

        for (int step = 0; step < total; step++) {
            int it = wid + (step >> 3) * NWSLOT;
            int chunk = step & 7, slot = step & 3;
            int b = it >> 12, grp = (it >> 3) & 511, je = it & 7;
            int row0 = (grp << 3) + halfr0;

            if (chunk == 0) {
#pragma unroll
                for (int rr = 0; rr < 4; rr++) {
                    float z  = __ldg(&g_src[row0 + rr]) + Md;
                    float lr = z > 0.f ? z : 0.2f * z;
                    float Cc = fmaxf(lr, 9e-15f);
                    float ca = expf(z - Cc), cb = expf(0.2f * z - Cc);
                    Ca2[rr] = pack2(ca, ca);
                    Cb2[rr] = pack2(cb, cb);
                    W0s[rr] = expf(9e-15f - Cc);
                }
            }

            // independent table loads + precompute BEFORE the wait
            int jg = (je << 9) + (chunk << 6) + (lsub << 2);
            double2 Qd  = *(const double2*)(sq  + jg);
            double2 Q2d = *(const double2*)(sq2 + jg);
            double2 H0d = *(const double2*)(sh0 + jg);
            double2 H1d = *(const double2*)(sh1 + jg);
            double2 H2d = *(const double2*)(sh2 + jg);
            ull qlo  = __double_as_longlong(Qd.x),  qhi  = __double_as_longlong(Qd.y);
            ull q2lo = __double_as_longlong(Q2d.x), q2hi = __double_as_longlong(Q2d.y);
            ull h0lo = __double_as_longlong(H0d.x), h0hi = __double_as_longlong(H0d.y);
            ull h1lo = __double_as_longlong(H1d.x), h1hi = __double_as_longlong(H1d.y);
            ull h2lo = __double_as_longlong(H2d.x), h2hi = __double_as_longlong(H2d.y);

            if (step + 3 < total) { issue(step + 3); cp_wait3(); }
            else                  { cp_wait0(); }
            __syncwarp();

            const int* st = wring + slot * 512;
#pragma unroll
            for (int rr = 0; rr < 4; rr++) {
                int4 aa = *(const int4*)(st + ((halfr0 + rr) << 6) + (lsub << 2));
                {
                    ull t1 = mul2(Ca2[rr], qlo), t2 = mul2(Cb2[rr], q2lo);
                    float m0, m1, n0, n1;
                    unpack2(m0, m1, t1); unpack2(n0, n1, t2);
                    float w0 = (aa.x > 0) ? fmaxf(m0, n0) : W0s[rr];
                    float w1 = (aa.y > 0) ? fmaxf(m1, n1) : W0s[rr];
                    ull wp = pack2(w0, w1);
                    ADD_X2(Sp[rr], Sp[rr], wp);
                    FMA_X2(T0p[rr], wp, h0lo, T0p[rr]);
                    FMA_X2(T1p[rr], wp, h1lo, T1p[rr]);
                    FMA_X2(T2p[rr], wp, h2lo, T2p[rr]);
                }
                {
                    ull t1 = mul2(Ca2[rr], qhi), t2 = mul2(Cb2[rr], q2hi);
                    float m0, m1, n0, n1;
                    unpack2(m0, m1, t1); unpack2(n0, n1, t2);
                    float w0 = (aa.z > 0) ? fmaxf(m0, n0) : W0s[rr];
                    float w1 = (aa.w > 0) ? fmaxf(m1, n1) : W0s[rr];
                    ull wp = pack2(w0, w1);
                    ADD_X2(Sp[rr], Sp[rr], wp);
                    FMA_X2(T0p[rr], wp, h0hi, T0p[rr]);
                    FMA_X2(T1p[rr], wp, h1hi, T1p[rr]);
                    FMA_X2(T2p[rr], wp, h2hi, T2p[rr]);
                }
            }

            if (chunk == 7) {
                float S[4], T0[4], T1[4], T2[4];
#pragma unroll
                for (int rr = 0; rr < 4; rr++) {
                    float lo, hi;
                    unpack2(lo, hi, Sp[rr]);  S[rr]  = lo + hi;
                    unpack2(lo, hi, T0p[rr]); T0[rr] = lo + hi;
                    unpack2(lo, hi, T1p[rr]); T1[rr] = lo + hi;
                    unpack2(lo, hi, T2p[rr]); T2[rr] = lo + hi;
                    Sp[rr] = 0ull; T0p[rr] = 0ull; T1p[rr] = 0ull; T2p[rr] = 0ull;
                }
#pragma unroll
                for (int o = 8; o > 0; o >>= 1) {
#pragma unroll
                    for (int rr = 0; rr < 4; rr++) {
                        S[rr]  += __shfl_xor_sync(0xffffffffu, S[rr],  o);
                        T0[rr] += __shfl_xor_sync(0xffffffffu, T0[rr], o);
                        T1[rr] += __shfl_xor_sync(0xffffffffu, T1[rr], o);
                        T2[rr] += __shfl_xor_sync(0xffffffffu, T2[rr], o);
                    }
                }
                if (lsub == 0) {
#pragma unroll
                    for (int rr = 0; rr < 4; rr++) {
                        int idx = (b << 12) + row0 + rr;
                        g_pS[je][idx]  = S[rr];
                        g_pT0[je][idx] = T0[rr];
                        g_pT1[je][idx] = T1[rr];
                        g_pT2[je][idx] = T2[rr];
                    }
                }
            }
        }
    }
    gsync();

    // ---------------- Phase 2: combine + ELU (blocks 0-31) ------------------
    if (bid < 32) {
        int t = bid * NTHR + tid;   // 0..16383 exactly
        float S = 0.f, v0 = 0.f, v1 = 0.f, v2 = 0.f;
#pragma unroll
        for (int e = 0; e < 8; e++) {
            S  += g_pS[e][t];
            v0 += g_pT0[e][t];
            v1 += g_pT1[e][t];
            v2 += g_pT2[e][t];
        }
        float inv = 1.f / S;
        v0 *= inv; v1 *= inv; v2 *= inv;
        v0 = v0 > 0.f ? v0 : expm1f(v0);
        v1 = v1 > 0.f ? v1 : expm1f(v1);
        v2 = v2 > 0.f ? v2 : expm1f(v2);
        g_x[t * 3 + 0] = v0;
        g_x[t * 3 + 1] = v1;
        g_x[t * 3 + 2] = v2;
    }
    gsync();

    // ---------------- Phase 3: FC (blocks 0-99, one k each) -----------------
    if (bid < FCO) {
        int k = bid;
        const float* wr = fcw + (size_t)k * (NE * 3);
        float4 wv[6];
#pragma unroll
        for (int i = 0; i < 6; i++)
            wv[i] = __ldg((const float4*)(wr + i * 2048 + tid * 4));

        float acc[NB] = {0.f, 0.f, 0.f, 0.f};
#pragma unroll
        for (int i = 0; i < 6; i++) {
            int n = i * 2048 + tid * 4;
#pragma unroll
            for (int b = 0; b < NB; b++) {
                float4 xv = *(const float4*)(g_x + b * NE * 3 + n);
                acc[b] = fmaf(wv[i].x, xv.x, fmaf(wv[i].y, xv.y,
                         fmaf(wv[i].z, xv.z, fmaf(wv[i].w, xv.w, acc[b]))));
            }
        }
#pragma unroll
        for (int o = 16; o > 0; o >>= 1)
#pragma unroll
            for (int b = 0; b < NB; b++)
                acc[b] += __shfl_xor_sync(0xffffffffu, acc[b], o);

        float* sred = (float*)ring;   // reuse ring smem
        if (lane == 0) {
#pragma unroll
            for (int b = 0; b < NB; b++) sred[warp * NB + b] = acc[b];
        }
        __syncthreads();
        if (tid < NB) {
            float s = __ldg(fcb + k);
#pragma unroll
            for (int ww = 0; ww < NWARP; ww++) s += sred[ww * NB + tid];
            out[tid * FCO + k] = s;
        }
    }
}

// ---------------------------------------------------------------------------
extern "C" void kernel_launch(void* const* d_in, const int* in_sizes, int n_in,
                              void* d_out, int out_size)
{
    const int*   adj = (const int*)d_in[0];
    const float* emb = (const float*)d_in[1];
    const float* W   = (const float*)d_in[2];
    const float* av  = (const float*)d_in[3];
    const float* fcw = (const float*)d_in[4];
    const float* fcb = (const float*)d_in[5];
    float* out = (float*)d_out;

    cudaFuncSetAttribute(k_all, cudaFuncAttributeMaxDynamicSharedMemorySize,
                         SMEM_BYTES);

    k_all<<<GRID, NTHR, SMEM_BYTES>>>(adj, emb, W, av, fcw, fcb, out);
}

// round 14
// speedup vs baseline: 1.0201x; 1.0201x over previous
#include <cuda_runtime.h>
#include <math.h>

#define NE   4096
#define EMB  64
#define NB   4
#define FCO  100
#define GRID 148
#define NTHR 512
#define NWARP 16
#define NWSLOT (GRID * NWARP)     // 2368 warp slots
#define NITEM 16384               // NB * 512 row-groups(8) * 8 j-eighths
#define TBL_FLOATS (5 * NE)       // q,q2,h0,h1,h2 = 80KB
#define RING_INTS (NWARP * 4 * 512)   // 16 warps x 4 slots x 2KB = 128KB
#define SMEM_BYTES (TBL_FLOATS * 4 + RING_INTS * 4)  // 208KB

// Scratch (allocation-free rule: __device__ globals)
__device__ float g_h0[NE], g_h1[NE], g_h2[NE];
__device__ float g_src[NE], g_dst[NE];
__device__ float g_x[NB * NE * 3];
__device__ float g_pS[8][NB * NE];
__device__ float g_pT0[8][NB * NE], g_pT1[8][NB * NE], g_pT2[8][NB * NE];
__device__ unsigned g_mbits = 0u;   // static init; atomicMax idempotent across replays
__device__ unsigned g_cnt = 0u;     // monotonic ticket barrier (no reset needed)

__device__ __forceinline__ unsigned enc_f(float f) {
    unsigned b = __float_as_uint(f);
    return (b & 0x80000000u) ? ~b : (b | 0x80000000u);
}
__device__ __forceinline__ float dec_f(unsigned u) {
    unsigned b = (u & 0x80000000u) ? (u & 0x7fffffffu) : ~u;
    return __uint_as_float(b);
}
__device__ __forceinline__ unsigned smem_u32(const void* p) {
    return (unsigned)__cvta_generic_to_shared(p);
}
__device__ __forceinline__ void cp16(unsigned dst, const void* src) {
    asm volatile("cp.async.cg.shared.global [%0], [%1], 16;" :: "r"(dst), "l"(src) : "memory");
}
__device__ __forceinline__ void cp_commit() {
    asm volatile("cp.async.commit_group;" ::: "memory");
}
__device__ __forceinline__ void cp_wait3() {
    asm volatile("cp.async.wait_group 3;" ::: "memory");
}
__device__ __forceinline__ void cp_wait0() {
    asm volatile("cp.async.wait_group 0;" ::: "memory");
}

// Grid-wide barrier: monotonic ticket epochs; all 148 CTAs resident (1 CTA/SM).
__device__ __forceinline__ void gsync() {
    __syncthreads();
    if (threadIdx.x == 0) {
        __threadfence();
        unsigned t = atomicAdd(&g_cnt, 1u);
        unsigned target = t - (t % (unsigned)GRID) + (unsigned)GRID;
        while ((int)(*(volatile unsigned*)&g_cnt - target) < 0)
            __nanosleep(64);
        __threadfence();
    }
    __syncthreads();
}

// Packed f32x2 helpers (sm_103a)
typedef unsigned long long ull;
__device__ __forceinline__ ull pack2(float lo, float hi) {
    ull r; asm("mov.b64 %0, {%1, %2};" : "=l"(r) : "f"(lo), "f"(hi)); return r;
}
__device__ __forceinline__ void unpack2(float& lo, float& hi, ull v) {
    asm("mov.b64 {%0, %1}, %2;" : "=f"(lo), "=f"(hi) : "l"(v));
}
__device__ __forceinline__ ull mul2(ull a, ull b) {
    ull d; asm("mul.rn.f32x2 %0, %1, %2;" : "=l"(d) : "l"(a), "l"(b)); return d;
}
#define FMA_X2(d, a, b, c) \
    asm("fma.rn.f32x2 %0, %1, %2, %3;" : "=l"(d) : "l"(a), "l"(b), "l"(c))
#define ADD_X2(d, a, b) \
    asm("add.rn.f32x2 %0, %1, %2;" : "=l"(d) : "l"(a), "l"(b))

// ---------------------------------------------------------------------------
// ONE persistent kernel:
//   ph0 prep (blocks 0-63) -> sync -> ph1 mainloop (all; FC blocks then stage
//   w into their idle ring) -> sync -> ph2 elu (blocks 100-131) while FC
//   blocks pull w smem->regs -> sync -> ph3 FC (blocks 0-99, L2-hot x)
//
// w staging layout: warp s holds w floats [s*768, s*768+768) at
//   ringf[s*2048 + l]  (l = local float).  Read inverse: w[f] ->
//   ringf[(f/768)*2048 + f%768].  (R13 bug: read assumed contiguous.)
// ---------------------------------------------------------------------------
__global__ void __launch_bounds__(NTHR, 1) k_all(
    const int*   __restrict__ adj,
    const float* __restrict__ emb,
    const float* __restrict__ W,
    const float* __restrict__ av,
    const float* __restrict__ fcw,
    const float* __restrict__ fcb,
    float*       __restrict__ out)
{
    extern __shared__ float sm[];
    float* sq  = sm;
    float* sq2 = sm + NE;
    float* sh0 = sm + 2 * NE;
    float* sh1 = sm + 3 * NE;
    float* sh2 = sm + 4 * NE;
    int*   ring = (int*)(sm + TBL_FLOATS);
    float* ringf = (float*)ring;

    int tid = threadIdx.x, bid = blockIdx.x;
    int warp = tid >> 5, lane = tid & 31;

    // ---------------- Phase 0: prep (blocks 0-63, 8 threads/row) -----------
    if (bid < 64) {
        int t = bid * NTHR + tid;          // 0..32767
        int row = t >> 3, sub = t & 7;
        const float4* e4 = (const float4*)(emb + row * EMB);
        float h0 = 0.f, h1 = 0.f, h2 = 0.f;
#pragma unroll
        for (int half = 0; half < 2; half++) {
            int fi = sub + half * 8;
            float4 ev = __ldg(e4 + fi);
            int k = fi * 4;
            h0 = fmaf(ev.x, __ldg(W + (k+0)*3+0), h0); h1 = fmaf(ev.x, __ldg(W + (k+0)*3+1), h1); h2 = fmaf(ev.x, __ldg(W + (k+0)*3+2), h2);
            h0 = fmaf(ev.y, __ldg(W + (k+1)*3+0), h0); h1 = fmaf(ev.y, __ldg(W + (k+1)*3+1), h1); h2 = fmaf(ev.y, __ldg(W + (k+1)*3+2), h2);
            h0 = fmaf(ev.z, __ldg(W + (k+2)*3+0), h0); h1 = fmaf(ev.z, __ldg(W + (k+2)*3+1), h1); h2 = fmaf(ev.z, __ldg(W + (k+2)*3+2), h2);
            h0 = fmaf(ev.w, __ldg(W + (k+3)*3+0), h0); h1 = fmaf(ev.w, __ldg(W + (k+3)*3+1), h1); h2 = fmaf(ev.w, __ldg(W + (k+3)*3+2), h2);
        }
#pragma unroll
        for (int o = 1; o <= 4; o <<= 1) {
            h0 += __shfl_xor_sync(0xffffffffu, h0, o);
            h1 += __shfl_xor_sync(0xffffffffu, h1, o);
            h2 += __shfl_xor_sync(0xffffffffu, h2, o);
        }
        if (sub == 0) {
            g_h0[row] = h0; g_h1[row] = h1; g_h2[row] = h2;
            g_src[row] = h0 * __ldg(av + 0) + h1 * __ldg(av + 1) + h2 * __ldg(av + 2);
            float d    = h0 * __ldg(av + 3) + h1 * __ldg(av + 4) + h2 * __ldg(av + 5);
            g_dst[row] = d;
            atomicMax(&g_mbits, enc_f(d));
        }
    }
    gsync();

    // ---------------- Phase 1: main adj stream (all blocks) ----------------
    {
        int lsub = lane & 15, halfr0 = (lane >> 4) << 2;
        int wid = bid * NWARP + warp;

        float Md = dec_f(g_mbits);
        for (int i = tid; i < NE; i += NTHR) {
            float d = g_dst[i];
            sq[i]  = expf(d - Md);
            sq2[i] = expf(0.2f * (d - Md));
            sh0[i] = g_h0[i]; sh1[i] = g_h1[i]; sh2[i] = g_h2[i];
        }
        __syncthreads();

        int nItems = 0;
        for (int it = wid; it < NITEM; it += NWSLOT) nItems++;
        int total = nItems * 8;   // wid < 2368 < 16384 -> total >= 8 always

        int* wring = ring + warp * 2048;              // 4 slots x 512 ints
        int cp_row = lane >> 2, cp_col = (lane & 3) << 2;   // ints
        unsigned cp_dst0 = smem_u32(wring) + (unsigned)((cp_row << 6) + cp_col) * 4u;

        auto issue = [&](int step) {
            int it = wid + (step >> 3) * NWSLOT;
            int slot = step & 3;
            int b = it >> 12, grp = (it >> 3) & 511, je = it & 7;
            const int* src = adj
                + ((size_t)((b << 12) + (grp << 3) + cp_row)) * NE
                + (je << 9) + ((step & 7) << 6) + cp_col;
            unsigned dst = cp_dst0 + (unsigned)slot * 2048u;
#pragma unroll
            for (int k = 0; k < 4; k++)
                cp16(dst + k * 64u, src + k * 16);
            cp_commit();
        };

        for (int p = 0; p < 3 && p < total; p++) issue(p);

        ull Sp[4] = {0,0,0,0}, T0p[4] = {0,0,0,0}, T1p[4] = {0,0,0,0}, T2p[4] = {0,0,0,0};
        ull Ca2[4], Cb2[4];
        float W0s[4];

        for (int step = 0; step < total; step++) {
            int it = wid + (step >> 3) * NWSLOT;
            int chunk = step & 7, slot = step & 3;
            int b = it >> 12, grp = (it >> 3) & 511, je = it & 7;
            int row0 = (grp << 3) + halfr0;

            if (chunk == 0) {
#pragma unroll
                for (int rr = 0; rr < 4; rr++) {
                    float z  = __ldg(&g_src[row0 + rr]) + Md;
                    float lr = z > 0.f ? z : 0.2f * z;
                    float Cc = fmaxf(lr, 9e-15f);
                    float ca = expf(z - Cc), cb = expf(0.2f * z - Cc);
                    Ca2[rr] = pack2(ca, ca);
                    Cb2[rr] = pack2(cb, cb);
                    W0s[rr] = expf(9e-15f - Cc);
                }
            }

            // independent table loads + precompute BEFORE the wait
            int jg = (je << 9) + (chunk << 6) + (lsub << 2);
            double2 Qd  = *(const double2*)(sq  + jg);
            double2 Q2d = *(const double2*)(sq2 + jg);
            double2 H0d = *(const double2*)(sh0 + jg);
            double2 H1d = *(const double2*)(sh1 + jg);
            double2 H2d = *(const double2*)(sh2 + jg);
            ull qlo  = __double_as_longlong(Qd.x),  qhi  = __double_as_longlong(Qd.y);
            ull q2lo = __double_as_longlong(Q2d.x), q2hi = __double_as_longlong(Q2d.y);
            ull h0lo = __double_as_longlong(H0d.x), h0hi = __double_as_longlong(H0d.y);
            ull h1lo = __double_as_longlong(H1d.x), h1hi = __double_as_longlong(H1d.y);
            ull h2lo = __double_as_longlong(H2d.x), h2hi = __double_as_longlong(H2d.y);

            if (step + 3 < total) { issue(step + 3); cp_wait3(); }
            else                  { cp_wait0(); }
            __syncwarp();

            const int* st = wring + slot * 512;
#pragma unroll
            for (int rr = 0; rr < 4; rr++) {
                int4 aa = *(const int4*)(st + ((halfr0 + rr) << 6) + (lsub << 2));
                {
                    ull t1 = mul2(Ca2[rr], qlo), t2 = mul2(Cb2[rr], q2lo);
                    float m0, m1, n0, n1;
                    unpack2(m0, m1, t1); unpack2(n0, n1, t2);
                    float w0 = (aa.x > 0) ? fmaxf(m0, n0) : W0s[rr];
                    float w1 = (aa.y > 0) ? fmaxf(m1, n1) : W0s[rr];
                    ull wp = pack2(w0, w1);
                    ADD_X2(Sp[rr], Sp[rr], wp);
                    FMA_X2(T0p[rr], wp, h0lo, T0p[rr]);
                    FMA_X2(T1p[rr], wp, h1lo, T1p[rr]);
                    FMA_X2(T2p[rr], wp, h2lo, T2p[rr]);
                }
                {
                    ull t1 = mul2(Ca2[rr], qhi), t2 = mul2(Cb2[rr], q2hi);
                    float m0, m1, n0, n1;
                    unpack2(m0, m1, t1); unpack2(n0, n1, t2);
                    float w0 = (aa.z > 0) ? fmaxf(m0, n0) : W0s[rr];
                    float w1 = (aa.w > 0) ? fmaxf(m1, n1) : W0s[rr];
                    ull wp = pack2(w0, w1);
                    ADD_X2(Sp[rr], Sp[rr], wp);
                    FMA_X2(T0p[rr], wp, h0hi, T0p[rr]);
                    FMA_X2(T1p[rr], wp, h1hi, T1p[rr]);
                    FMA_X2(T2p[rr], wp, h2hi, T2p[rr]);
                }
            }

            if (chunk == 7) {
                float S[4], T0[4], T1[4], T2[4];
#pragma unroll
                for (int rr = 0; rr < 4; rr++) {
                    float lo, hi;
                    unpack2(lo, hi, Sp[rr]);  S[rr]  = lo + hi;
                    unpack2(lo, hi, T0p[rr]); T0[rr] = lo + hi;
                    unpack2(lo, hi, T1p[rr]); T1[rr] = lo + hi;
                    unpack2(lo, hi, T2p[rr]); T2[rr] = lo + hi;
                    Sp[rr] = 0ull; T0p[rr] = 0ull; T1p[rr] = 0ull; T2p[rr] = 0ull;
                }
#pragma unroll
                for (int o = 8; o > 0; o >>= 1) {
#pragma unroll
                    for (int rr = 0; rr < 4; rr++) {
                        S[rr]  += __shfl_xor_sync(0xffffffffu, S[rr],  o);
                        T0[rr] += __shfl_xor_sync(0xffffffffu, T0[rr], o);
                        T1[rr] += __shfl_xor_sync(0xffffffffu, T1[rr], o);
                        T2[rr] += __shfl_xor_sync(0xffffffffu, T2[rr], o);
                    }
                }
                if (lsub == 0) {
#pragma unroll
                    for (int rr = 0; rr < 4; rr++) {
                        int idx = (b << 12) + row0 + rr;
                        g_pS[je][idx]  = S[rr];
                        g_pT0[je][idx] = T0[rr];
                        g_pT1[je][idx] = T1[rr];
                        g_pT2[je][idx] = T2[rr];
                    }
                }
            }
        }

        // ---- FC blocks: stage their w row into OWN (now idle) ring region ----
        // warp s stages w floats [s*768, s*768+768) at ringf[s*2048 + l].
        if (bid < FCO) {
            const float* wsrc = fcw + (size_t)bid * (NE * 3) + warp * 768 + lane * 4;
            unsigned wdst = smem_u32(ringf + warp * 2048) + (unsigned)(lane * 16);
#pragma unroll
            for (int i = 0; i < 6; i++)
                cp16(wdst + (unsigned)i * 512u, wsrc + i * 128);
            cp_commit();
        }
    }
    gsync();

    // ---------------- Phase 2 window ----------------------------------------
    // blocks 100-131: combine + ELU.  FC blocks (0-99): pull w smem -> regs.
    float4 wv[6];
    if (bid < FCO) {
        cp_wait0();
        __syncthreads();   // cross-warp smem visibility of staged w
#pragma unroll
        for (int i = 0; i < 6; i++) {
            // w float index f -> ringf[(f/768)*2048 + f%768]  (staged layout)
            int f = i * 2048 + tid * 4;
            int s = f / 768;
            int l = f - s * 768;
            wv[i] = *(const float4*)(ringf + s * 2048 + l);
        }
    } else if (bid < 132) {
        int t = (bid - 100) * NTHR + tid;   // 0..16383 exactly
        float S = 0.f, v0 = 0.f, v1 = 0.f, v2 = 0.f;
#pragma unroll
        for (int e = 0; e < 8; e++) {
            S  += g_pS[e][t];
            v0 += g_pT0[e][t];
            v1 += g_pT1[e][t];
            v2 += g_pT2[e][t];
        }
        float inv = 1.f / S;
        v0 *= inv; v1 *= inv; v2 *= inv;
        v0 = v0 > 0.f ? v0 : expm1f(v0);
        v1 = v1 > 0.f ? v1 : expm1f(v1);
        v2 = v2 > 0.f ? v2 : expm1f(v2);
        g_x[t * 3 + 0] = v0;
        g_x[t * 3 + 1] = v1;
        g_x[t * 3 + 2] = v2;
    }
    gsync();

    // ---------------- Phase 3: FC (blocks 0-99, one k each) -----------------
    if (bid < FCO) {
        int k = bid;
        float acc[NB] = {0.f, 0.f, 0.f, 0.f};
#pragma unroll
        for (int i = 0; i < 6; i++) {
            int n = i * 2048 + tid * 4;
#pragma unroll
            for (int b = 0; b < NB; b++) {
                float4 xv = *(const float4*)(g_x + b * NE * 3 + n);
                acc[b] = fmaf(wv[i].x, xv.x, fmaf(wv[i].y, xv.y,
                         fmaf(wv[i].z, xv.z, fmaf(wv[i].w, xv.w, acc[b]))));
            }
        }
#pragma unroll
        for (int o = 16; o > 0; o >>= 1)
#pragma unroll
            for (int b = 0; b < NB; b++)
                acc[b] += __shfl_xor_sync(0xffffffffu, acc[b], o);

        float* sred = (float*)ring;   // reuse ring smem (w already in regs)
        __syncthreads();
        if (lane == 0) {
#pragma unroll
            for (int b = 0; b < NB; b++) sred[warp * NB + b] = acc[b];
        }
        __syncthreads();
        if (tid < NB) {
            float s = __ldg(fcb + k);
#pragma unroll
            for (int ww = 0; ww < NWARP; ww++) s += sred[ww * NB + tid];
            out[tid * FCO + k] = s;
        }
    }
}

// ---------------------------------------------------------------------------
extern "C" void kernel_launch(void* const* d_in, const int* in_sizes, int n_in,
                              void* d_out, int out_size)
{
    const int*   adj = (const int*)d_in[0];
    const float* emb = (const float*)d_in[1];
    const float* W   = (const float*)d_in[2];
    const float* av  = (const float*)d_in[3];
    const float* fcw = (const float*)d_in[4];
    const float* fcb = (const float*)d_in[5];
    float* out = (float*)d_out;

    cudaFuncSetAttribute(k_all, cudaFuncAttributeMaxDynamicSharedMemorySize,
                         SMEM_BYTES);

    k_all<<<GRID, NTHR, SMEM_BYTES>>>(adj, emb, W, av, fcw, fcb, out);
}

// round 15
// speedup vs baseline: 1.0238x; 1.0036x over previous
#include <cuda_runtime.h>
#include <math.h>

#define NE   4096
#define EMB  64
#define NB   4
#define FCO  100
#define GRID 148
#define NTHR 512
#define NWARP 16
#define NWSLOT (GRID * NWARP)     // 2368 warp slots
#define NITEM 16384               // NB * 512 row-groups(8) * 8 j-eighths
#define TBL_FLOATS (5 * NE)       // q,q2,h0,h1,h2 = 80KB
#define RING_INTS (NWARP * 4 * 512)   // 16 warps x 4 slots x 2KB = 128KB
#define SMEM_BYTES (TBL_FLOATS * 4 + RING_INTS * 4)  // 208KB

// Scratch (allocation-free rule: __device__ globals)
__device__ float g_h0[NE], g_h1[NE], g_h2[NE];
__device__ float g_src[NE], g_dst[NE];
__device__ float g_x[NB * NE * 3];
__device__ float g_pS[8][NB * NE];
__device__ float g_pT0[8][NB * NE], g_pT1[8][NB * NE], g_pT2[8][NB * NE];
__device__ unsigned g_mbits = 0u;   // static init; atomicMax idempotent across replays
__device__ unsigned g_cnt = 0u;     // monotonic ticket barrier (no reset needed)

__device__ __forceinline__ unsigned enc_f(float f) {
    unsigned b = __float_as_uint(f);
    return (b & 0x80000000u) ? ~b : (b | 0x80000000u);
}
__device__ __forceinline__ float dec_f(unsigned u) {
    unsigned b = (u & 0x80000000u) ? (u & 0x7fffffffu) : ~u;
    return __uint_as_float(b);
}
__device__ __forceinline__ unsigned smem_u32(const void* p) {
    return (unsigned)__cvta_generic_to_shared(p);
}
__device__ __forceinline__ void cp16(unsigned dst, const void* src) {
    asm volatile("cp.async.cg.shared.global [%0], [%1], 16;" :: "r"(dst), "l"(src) : "memory");
}
__device__ __forceinline__ void cp_commit() {
    asm volatile("cp.async.commit_group;" ::: "memory");
}
__device__ __forceinline__ void cp_wait3() {
    asm volatile("cp.async.wait_group 3;" ::: "memory");
}
__device__ __forceinline__ void cp_wait0() {
    asm volatile("cp.async.wait_group 0;" ::: "memory");
}

// Grid-wide barrier: monotonic ticket epochs; all 148 CTAs resident (1 CTA/SM).
__device__ __forceinline__ void gsync() {
    __syncthreads();
    if (threadIdx.x == 0) {
        __threadfence();
        unsigned t = atomicAdd(&g_cnt, 1u);
        unsigned target = t - (t % (unsigned)GRID) + (unsigned)GRID;
        while ((int)(*(volatile unsigned*)&g_cnt - target) < 0)
            __nanosleep(64);
        __threadfence();
    }
    __syncthreads();
}

// Packed f32x2 helpers (sm_103a)
typedef unsigned long long ull;
__device__ __forceinline__ ull pack2(float lo, float hi) {
    ull r; asm("mov.b64 %0, {%1, %2};" : "=l"(r) : "f"(lo), "f"(hi)); return r;
}
__device__ __forceinline__ void unpack2(float& lo, float& hi, ull v) {
    asm("mov.b64 {%0, %1}, %2;" : "=f"(lo), "=f"(hi) : "l"(v));
}
__device__ __forceinline__ ull mul2(ull a, ull b) {
    ull d; asm("mul.rn.f32x2 %0, %1, %2;" : "=l"(d) : "l"(a), "l"(b)); return d;
}
#define FMA_X2(d, a, b, c) \
    asm("fma.rn.f32x2 %0, %1, %2, %3;" : "=l"(d) : "l"(a), "l"(b), "l"(c))
#define ADD_X2(d, a, b) \
    asm("add.rn.f32x2 %0, %1, %2;" : "=l"(d) : "l"(a), "l"(b))

// ---------------------------------------------------------------------------
// ONE persistent kernel:
//   ph0 prep (blocks 0-63) -> sync -> ph1 mainloop (item x unrolled-8-chunk,
//   constant slots; FC blocks then stage w into their idle ring) -> sync ->
//   ph2 elu (blocks 100-131) while FC blocks pull w smem->regs -> sync ->
//   ph3 FC (blocks 0-99, L2-hot x)
// ---------------------------------------------------------------------------
__global__ void __launch_bounds__(NTHR, 1) k_all(
    const int*   __restrict__ adj,
    const float* __restrict__ emb,
    const float* __restrict__ W,
    const float* __restrict__ av,
    const float* __restrict__ fcw,
    const float* __restrict__ fcb,
    float*       __restrict__ out)
{
    extern __shared__ float sm[];
    float* sq  = sm;
    float* sq2 = sm + NE;
    float* sh0 = sm + 2 * NE;
    float* sh1 = sm + 3 * NE;
    float* sh2 = sm + 4 * NE;
    int*   ring = (int*)(sm + TBL_FLOATS);
    float* ringf = (float*)ring;

    int tid = threadIdx.x, bid = blockIdx.x;
    int warp = tid >> 5, lane = tid & 31;

    // ---------------- Phase 0: prep (blocks 0-63, 8 threads/row) -----------
    if (bid < 64) {
        int t = bid * NTHR + tid;          // 0..32767
        int row = t >> 3, sub = t & 7;
        const float4* e4 = (const float4*)(emb + row * EMB);
        float h0 = 0.f, h1 = 0.f, h2 = 0.f;
#pragma unroll
        for (int half = 0; half < 2; half++) {
            int fi = sub + half * 8;
            float4 ev = __ldg(e4 + fi);
            int k = fi * 4;
            h0 = fmaf(ev.x, __ldg(W + (k+0)*3+0), h0); h1 = fmaf(ev.x, __ldg(W + (k+0)*3+1), h1); h2 = fmaf(ev.x, __ldg(W + (k+0)*3+2), h2);
            h0 = fmaf(ev.y, __ldg(W + (k+1)*3+0), h0); h1 = fmaf(ev.y, __ldg(W + (k+1)*3+1), h1); h2 = fmaf(ev.y, __ldg(W + (k+1)*3+2), h2);
            h0 = fmaf(ev.z, __ldg(W + (k+2)*3+0), h0); h1 = fmaf(ev.z, __ldg(W + (k+2)*3+1), h1); h2 = fmaf(ev.z, __ldg(W + (k+2)*3+2), h2);
            h0 = fmaf(ev.w, __ldg(W + (k+3)*3+0), h0); h1 = fmaf(ev.w, __ldg(W + (k+3)*3+1), h1); h2 = fmaf(ev.w, __ldg(W + (k+3)*3+2), h2);
        }
#pragma unroll
        for (int o = 1; o <= 4; o <<= 1) {
            h0 += __shfl_xor_sync(0xffffffffu, h0, o);
            h1 += __shfl_xor_sync(0xffffffffu, h1, o);
            h2 += __shfl_xor_sync(0xffffffffu, h2, o);
        }
        if (sub == 0) {
            g_h0[row] = h0; g_h1[row] = h1; g_h2[row] = h2;
            g_src[row] = h0 * __ldg(av + 0) + h1 * __ldg(av + 1) + h2 * __ldg(av + 2);
            float d    = h0 * __ldg(av + 3) + h1 * __ldg(av + 4) + h2 * __ldg(av + 5);
            g_dst[row] = d;
            atomicMax(&g_mbits, enc_f(d));
        }
    }
    gsync();

    // ---------------- Phase 1: main adj stream (all blocks) ----------------
    {
        int lsub = lane & 15, halfr0 = (lane >> 4) << 2;
        int wid = bid * NWARP + warp;

        float Md = dec_f(g_mbits);
        for (int i = tid; i < NE; i += NTHR) {
            float d = g_dst[i];
            sq[i]  = expf(d - Md);
            sq2[i] = expf(0.2f * (d - Md));
            sh0[i] = g_h0[i]; sh1[i] = g_h1[i]; sh2[i] = g_h2[i];
        }
        __syncthreads();

        int nItems = 0;
        for (int it = wid; it < NITEM; it += NWSLOT) nItems++;

        int* wring = ring + warp * 2048;              // 4 slots x 512 ints
        int cp_row = lane >> 2, cp_col = (lane & 3) << 2;   // ints
        unsigned cp_dst0 = smem_u32(wring) + (unsigned)((cp_row << 6) + cp_col) * 4u;

        // issue 4 cp16 from src (one 64-int chunk) into ring slot
        auto issue4 = [&](const int* src, int slot) {
            unsigned dst = cp_dst0 + (unsigned)slot * 2048u;
#pragma unroll
            for (int k = 0; k < 4; k++)
                cp16(dst + k * 64u, src + k * 16);
            cp_commit();
        };
        auto cpbase = [&](int it) -> const int* {
            int b = it >> 12, grp = (it >> 3) & 511, je = it & 7;
            return adj + ((size_t)((b << 12) + (grp << 3) + cp_row)) * NE
                       + (je << 9) + cp_col;
        };

        // prologue: item0 chunks 0,1,2 -> slots 0,1,2
        {
            const int* s0 = cpbase(wid);
            issue4(s0,       0);
            issue4(s0 + 64,  1);
            issue4(s0 + 128, 2);
        }

        ull Sp[4] = {0,0,0,0}, T0p[4] = {0,0,0,0}, T1p[4] = {0,0,0,0}, T2p[4] = {0,0,0,0};

        int it = wid;
        const int* curSrc = cpbase(it);
        for (int itIdx = 0; itIdx < nItems; itIdx++) {
            bool hn = (itIdx + 1 < nItems);
            int b = it >> 12, grp = (it >> 3) & 511, je = it & 7;
            int row0 = (grp << 3) + halfr0;
            int nit = it + NWSLOT;
            const int* nextSrc = hn ? cpbase(nit) : curSrc;

            // per-item row constants
            ull Ca2[4], Cb2[4];
            float W0s[4];
#pragma unroll
            for (int rr = 0; rr < 4; rr++) {
                float z  = __ldg(&g_src[row0 + rr]) + Md;
                float lr = z > 0.f ? z : 0.2f * z;
                float Cc = fmaxf(lr, 9e-15f);
                float ca = expf(z - Cc), cb = expf(0.2f * z - Cc);
                Ca2[rr] = pack2(ca, ca);
                Cb2[rr] = pack2(cb, cb);
                W0s[rr] = expf(9e-15f - Cc);
            }

            int jg0 = (je << 9) + (lsub << 2);
            const float* tq  = sq  + jg0;
            const float* tq2 = sq2 + jg0;
            const float* th0 = sh0 + jg0;
            const float* th1 = sh1 + jg0;
            const float* th2 = sh2 + jg0;

#pragma unroll
            for (int c = 0; c < 8; c++) {
                // independent table loads BEFORE the wait (constant offsets)
                double2 Qd  = *(const double2*)(tq  + c * 64);
                double2 Q2d = *(const double2*)(tq2 + c * 64);
                double2 H0d = *(const double2*)(th0 + c * 64);
                double2 H1d = *(const double2*)(th1 + c * 64);
                double2 H2d = *(const double2*)(th2 + c * 64);
                ull qlo  = __double_as_longlong(Qd.x),  qhi  = __double_as_longlong(Qd.y);
                ull q2lo = __double_as_longlong(Q2d.x), q2hi = __double_as_longlong(Q2d.y);
                ull h0lo = __double_as_longlong(H0d.x), h0hi = __double_as_longlong(H0d.y);
                ull h1lo = __double_as_longlong(H1d.x), h1hi = __double_as_longlong(H1d.y);
                ull h2lo = __double_as_longlong(H2d.x), h2hi = __double_as_longlong(H2d.y);

                // prefetch step+3 (constant slots: (c+3)&3 / (c-5)&3)
                if (c < 5) {
                    issue4(curSrc + (c + 3) * 64, (c + 3) & 3);
                    cp_wait3();
                } else if (hn) {
                    issue4(nextSrc + (c - 5) * 64, (c - 5) & 3);
                    cp_wait3();
                } else {
                    cp_wait0();
                }
                __syncwarp();

                const int* st = wring + (c & 3) * 512;
#pragma unroll
                for (int rr = 0; rr < 4; rr++) {
                    int4 aa = *(const int4*)(st + ((halfr0 + rr) << 6) + (lsub << 2));
                    {
                        ull t1 = mul2(Ca2[rr], qlo), t2 = mul2(Cb2[rr], q2lo);
                        float m0, m1, n0, n1;
                        unpack2(m0, m1, t1); unpack2(n0, n1, t2);
                        float w0 = (aa.x > 0) ? fmaxf(m0, n0) : W0s[rr];
                        float w1 = (aa.y > 0) ? fmaxf(m1, n1) : W0s[rr];
                        ull wp = pack2(w0, w1);
                        ADD_X2(Sp[rr], Sp[rr], wp);
                        FMA_X2(T0p[rr], wp, h0lo, T0p[rr]);
                        FMA_X2(T1p[rr], wp, h1lo, T1p[rr]);
                        FMA_X2(T2p[rr], wp, h2lo, T2p[rr]);
                    }
                    {
                        ull t1 = mul2(Ca2[rr], qhi), t2 = mul2(Cb2[rr], q2hi);
                        float m0, m1, n0, n1;
                        unpack2(m0, m1, t1); unpack2(n0, n1, t2);
                        float w0 = (aa.z > 0) ? fmaxf(m0, n0) : W0s[rr];
                        float w1 = (aa.w > 0) ? fmaxf(m1, n1) : W0s[rr];
                        ull wp = pack2(w0, w1);
                        ADD_X2(Sp[rr], Sp[rr], wp);
                        FMA_X2(T0p[rr], wp, h0hi, T0p[rr]);
                        FMA_X2(T1p[rr], wp, h1hi, T1p[rr]);
                        FMA_X2(T2p[rr], wp, h2hi, T2p[rr]);
                    }
                }
            }

            // per-item epilogue: fold packed pairs, half-warp reduce, store
            {
                float S[4], T0[4], T1[4], T2[4];
#pragma unroll
                for (int rr = 0; rr < 4; rr++) {
                    float lo, hi;
                    unpack2(lo, hi, Sp[rr]);  S[rr]  = lo + hi;
                    unpack2(lo, hi, T0p[rr]); T0[rr] = lo + hi;
                    unpack2(lo, hi, T1p[rr]); T1[rr] = lo + hi;
                    unpack2(lo, hi, T2p[rr]); T2[rr] = lo + hi;
                    Sp[rr] = 0ull; T0p[rr] = 0ull; T1p[rr] = 0ull; T2p[rr] = 0ull;
                }
#pragma unroll
                for (int o = 8; o > 0; o >>= 1) {
#pragma unroll
                    for (int rr = 0; rr < 4; rr++) {
                        S[rr]  += __shfl_xor_sync(0xffffffffu, S[rr],  o);
                        T0[rr] += __shfl_xor_sync(0xffffffffu, T0[rr], o);
                        T1[rr] += __shfl_xor_sync(0xffffffffu, T1[rr], o);
                        T2[rr] += __shfl_xor_sync(0xffffffffu, T2[rr], o);
                    }
                }
                if (lsub == 0) {
#pragma unroll
                    for (int rr = 0; rr < 4; rr++) {
                        int idx = (b << 12) + row0 + rr;
                        g_pS[je][idx]  = S[rr];
                        g_pT0[je][idx] = T0[rr];
                        g_pT1[je][idx] = T1[rr];
                        g_pT2[je][idx] = T2[rr];
                    }
                }
            }

            it = nit;
            curSrc = nextSrc;
        }

        // ---- FC blocks: stage their w row into OWN (now idle) ring region ----
        // warp s stages w floats [s*768, s*768+768) at ringf[s*2048 + l].
        if (bid < FCO) {
            const float* wsrc = fcw + (size_t)bid * (NE * 3) + warp * 768 + lane * 4;
            unsigned wdst = smem_u32(ringf + warp * 2048) + (unsigned)(lane * 16);
#pragma unroll
            for (int i = 0; i < 6; i++)
                cp16(wdst + (unsigned)i * 512u, wsrc + i * 128);
            cp_commit();
        }
    }
    gsync();

    // ---------------- Phase 2 window ----------------------------------------
    // blocks 100-131: combine + ELU.  FC blocks (0-99): pull w smem -> regs.
    float4 wv[6];
    if (bid < FCO) {
        cp_wait0();
        __syncthreads();   // cross-warp smem visibility of staged w
#pragma unroll
        for (int i = 0; i < 6; i++) {
            // w float index f -> ringf[(f/768)*2048 + f%768]  (staged layout)
            int f = i * 2048 + tid * 4;
            int s = f / 768;
            int l = f - s * 768;
            wv[i] = *(const float4*)(ringf + s * 2048 + l);
        }
    } else if (bid < 132) {
        int t = (bid - 100) * NTHR + tid;   // 0..16383 exactly
        float S = 0.f, v0 = 0.f, v1 = 0.f, v2 = 0.f;
#pragma unroll
        for (int e = 0; e < 8; e++) {
            S  += g_pS[e][t];
            v0 += g_pT0[e][t];
            v1 += g_pT1[e][t];
            v2 += g_pT2[e][t];
        }
        float inv = 1.f / S;
        v0 *= inv; v1 *= inv; v2 *= inv;
        v0 = v0 > 0.f ? v0 : expm1f(v0);
        v1 = v1 > 0.f ? v1 : expm1f(v1);
        v2 = v2 > 0.f ? v2 : expm1f(v2);
        g_x[t * 3 + 0] = v0;
        g_x[t * 3 + 1] = v1;
        g_x[t * 3 + 2] = v2;
    }
    gsync();

    // ---------------- Phase 3: FC (blocks 0-99, one k each) -----------------
    if (bid < FCO) {
        int k = bid;
        float acc[NB] = {0.f, 0.f, 0.f, 0.f};
#pragma unroll
        for (int i = 0; i < 6; i++) {
            int n = i * 2048 + tid * 4;
#pragma unroll
            for (int b = 0; b < NB; b++) {
                float4 xv = *(const float4*)(g_x + b * NE * 3 + n);
                acc[b] = fmaf(wv[i].x, xv.x, fmaf(wv[i].y, xv.y,
                         fmaf(wv[i].z, xv.z, fmaf(wv[i].w, xv.w, acc[b]))));
            }
        }
#pragma unroll
        for (int o = 16; o > 0; o >>= 1)
#pragma unroll
            for (int b = 0; b < NB; b++)
                acc[b] += __shfl_xor_sync(0xffffffffu, acc[b], o);

        float* sred = (float*)ring;   // reuse ring smem (w already in regs)
        __syncthreads();
        if (lane == 0) {
#pragma unroll
            for (int b = 0; b < NB; b++) sred[warp * NB + b] = acc[b];
        }
        __syncthreads();
        if (tid < NB) {
            float s = __ldg(fcb + k);
#pragma unroll
            for (int ww = 0; ww < NWARP; ww++) s += sred[ww * NB + tid];
            out[tid * FCO + k] = s;
        }
    }
}

// ---------------------------------------------------------------------------
extern "C" void kernel_launch(void* const* d_in, const int* in_sizes, int n_in,
                              void* d_out, int out_size)
{
    const int*   adj = (const int*)d_in[0];
    const float* emb = (const float*)d_in[1];
    const float* W   = (const float*)d_in[2];
    const float* av  = (const float*)d_in[3];
    const float* fcw = (const float*)d_in[4];
    const float* fcb = (const float*)d_in[5];
    float* out = (float*)d_out;

    cudaFuncSetAttribute(k_all, cudaFuncAttributeMaxDynamicSharedMemorySize,
                         SMEM_BYTES);

    k_all<<<GRID, NTHR, SMEM_BYTES>>>(adj, emb, W, av, fcw, fcb, out);
}

// round 16
// speedup vs baseline: 1.0588x; 1.0342x over previous
#include <cuda_runtime.h>
#include <math.h>

#define NE   4096
#define EMB  64
#define NB   4
#define FCO  100
#define GRID 148
#define NTHR 512
#define NWARP 16
#define NGRP 4                     // CTA groups; group g owns je in {2g, 2g+1}
#define CTA_PER_GRP 37
#define NWSLOT_G (CTA_PER_GRP * NWARP)   // 592 warp slots per group
#define NITEM_G 4096               // items per group: NB * 512 grp * 2 jsub
#define NSLOT 6                    // ring slots per warp
#define TBL_FLOATS (5 * 1024)      // q,q2,h0,h1,h2 for this CTA's 1024-j range = 20KB
#define RING_INTS (NWARP * NSLOT * 512)   // 16 warps x 6 slots x 2KB = 192KB
#define SMEM_BYTES (TBL_FLOATS * 4 + RING_INTS * 4)  // 212KB
#define WRING_INTS (NSLOT * 512)   // 3072 ints per warp

// Scratch (allocation-free rule: __device__ globals)
__device__ float g_h0[NE], g_h1[NE], g_h2[NE];
__device__ float g_src[NE], g_dst[NE];
__device__ float g_x[NB * NE * 3];
__device__ float g_pS[8][NB * NE];
__device__ float g_pT0[8][NB * NE], g_pT1[8][NB * NE], g_pT2[8][NB * NE];
__device__ unsigned g_mbits = 0u;   // static init; atomicMax idempotent across replays
__device__ unsigned g_cnt = 0u;     // monotonic ticket barrier (no reset needed)

__device__ __forceinline__ unsigned enc_f(float f) {
    unsigned b = __float_as_uint(f);
    return (b & 0x80000000u) ? ~b : (b | 0x80000000u);
}
__device__ __forceinline__ float dec_f(unsigned u) {
    unsigned b = (u & 0x80000000u) ? (u & 0x7fffffffu) : ~u;
    return __uint_as_float(b);
}
__device__ __forceinline__ unsigned smem_u32(const void* p) {
    return (unsigned)__cvta_generic_to_shared(p);
}
__device__ __forceinline__ void cp16(unsigned dst, const void* src) {
    asm volatile("cp.async.cg.shared.global [%0], [%1], 16;" :: "r"(dst), "l"(src) : "memory");
}
__device__ __forceinline__ void cp_commit() {
    asm volatile("cp.async.commit_group;" ::: "memory");
}
__device__ __forceinline__ void cp_wait5() {
    asm volatile("cp.async.wait_group 5;" ::: "memory");
}
__device__ __forceinline__ void cp_wait0() {
    asm volatile("cp.async.wait_group 0;" ::: "memory");
}

// Grid-wide barrier: monotonic ticket epochs; all 148 CTAs resident (1 CTA/SM).
__device__ __forceinline__ void gsync() {
    __syncthreads();
    if (threadIdx.x == 0) {
        __threadfence();
        unsigned t = atomicAdd(&g_cnt, 1u);
        unsigned target = t - (t % (unsigned)GRID) + (unsigned)GRID;
        while ((int)(*(volatile unsigned*)&g_cnt - target) < 0)
            __nanosleep(64);
        __threadfence();
    }
    __syncthreads();
}

// Packed f32x2 helpers (sm_103a)
typedef unsigned long long ull;
__device__ __forceinline__ ull pack2(float lo, float hi) {
    ull r; asm("mov.b64 %0, {%1, %2};" : "=l"(r) : "f"(lo), "f"(hi)); return r;
}
__device__ __forceinline__ void unpack2(float& lo, float& hi, ull v) {
    asm("mov.b64 {%0, %1}, %2;" : "=f"(lo), "=f"(hi) : "l"(v));
}
__device__ __forceinline__ ull mul2(ull a, ull b) {
    ull d; asm("mul.rn.f32x2 %0, %1, %2;" : "=l"(d) : "l"(a), "l"(b)); return d;
}
#define FMA_X2(d, a, b, c) \
    asm("fma.rn.f32x2 %0, %1, %2, %3;" : "=l"(d) : "l"(a), "l"(b), "l"(c))
#define ADD_X2(d, a, b) \
    asm("add.rn.f32x2 %0, %1, %2;" : "=l"(d) : "l"(a), "l"(b))

// ---------------------------------------------------------------------------
// ONE persistent kernel. Phase 1 item space is partitioned by CTA group:
// group g = bid/37 owns je in {2g, 2g+1}; per-CTA tables cover only that
// 1024-j range (20KB), freeing SMEM for a 6-slot ring (prefetch distance 5,
// 10KB in flight per warp).
// ---------------------------------------------------------------------------
__global__ void __launch_bounds__(NTHR, 1) k_all(
    const int*   __restrict__ adj,
    const float* __restrict__ emb,
    const float* __restrict__ W,
    const float* __restrict__ av,
    const float* __restrict__ fcw,
    const float* __restrict__ fcb,
    float*       __restrict__ out)
{
    extern __shared__ float sm[];
    float* sq  = sm;            // 1024
    float* sq2 = sm + 1024;
    float* sh0 = sm + 2048;
    float* sh1 = sm + 3072;
    float* sh2 = sm + 4096;
    int*   ring = (int*)(sm + TBL_FLOATS);
    float* ringf = (float*)ring;

    int tid = threadIdx.x, bid = blockIdx.x;
    int warp = tid >> 5, lane = tid & 31;

    // ---------------- Phase 0: prep (blocks 0-63, 8 threads/row) -----------
    if (bid < 64) {
        int t = bid * NTHR + tid;          // 0..32767
        int row = t >> 3, sub = t & 7;
        const float4* e4 = (const float4*)(emb + row * EMB);
        float h0 = 0.f, h1 = 0.f, h2 = 0.f;
#pragma unroll
        for (int half = 0; half < 2; half++) {
            int fi = sub + half * 8;
            float4 ev = __ldg(e4 + fi);
            int k = fi * 4;
            h0 = fmaf(ev.x, __ldg(W + (k+0)*3+0), h0); h1 = fmaf(ev.x, __ldg(W + (k+0)*3+1), h1); h2 = fmaf(ev.x, __ldg(W + (k+0)*3+2), h2);
            h0 = fmaf(ev.y, __ldg(W + (k+1)*3+0), h0); h1 = fmaf(ev.y, __ldg(W + (k+1)*3+1), h1); h2 = fmaf(ev.y, __ldg(W + (k+1)*3+2), h2);
            h0 = fmaf(ev.z, __ldg(W + (k+2)*3+0), h0); h1 = fmaf(ev.z, __ldg(W + (k+2)*3+1), h1); h2 = fmaf(ev.z, __ldg(W + (k+2)*3+2), h2);
            h0 = fmaf(ev.w, __ldg(W + (k+3)*3+0), h0); h1 = fmaf(ev.w, __ldg(W + (k+3)*3+1), h1); h2 = fmaf(ev.w, __ldg(W + (k+3)*3+2), h2);
        }
#pragma unroll
        for (int o = 1; o <= 4; o <<= 1) {
            h0 += __shfl_xor_sync(0xffffffffu, h0, o);
            h1 += __shfl_xor_sync(0xffffffffu, h1, o);
            h2 += __shfl_xor_sync(0xffffffffu, h2, o);
        }
        if (sub == 0) {
            g_h0[row] = h0; g_h1[row] = h1; g_h2[row] = h2;
            g_src[row] = h0 * __ldg(av + 0) + h1 * __ldg(av + 1) + h2 * __ldg(av + 2);
            float d    = h0 * __ldg(av + 3) + h1 * __ldg(av + 4) + h2 * __ldg(av + 5);
            g_dst[row] = d;
            atomicMax(&g_mbits, enc_f(d));
        }
    }
    gsync();

    // ---------------- Phase 1: main adj stream (all blocks) ----------------
    {
        int g = bid / CTA_PER_GRP;               // 0..3
        int cg = bid - g * CTA_PER_GRP;          // 0..36
        int wslot = cg * NWARP + warp;           // 0..591
        int lsub = lane & 15, halfr0 = (lane >> 4) << 2;

        float Md = dec_f(g_mbits);
        // tables for this CTA's 1024-j range: jglob = (g<<10) + i
        for (int i = tid; i < 1024; i += NTHR) {
            int jglob = (g << 10) + i;
            float d = g_dst[jglob];
            sq[i]  = expf(d - Md);
            sq2[i] = expf(0.2f * (d - Md));
            sh0[i] = g_h0[jglob]; sh1[i] = g_h1[jglob]; sh2[i] = g_h2[jglob];
        }
        __syncthreads();

        int nItems = 0;
        for (int it = wslot; it < NITEM_G; it += NWSLOT_G) nItems++;

        int* wring = ring + warp * WRING_INTS;        // 6 slots x 512 ints
        int cp_row = lane >> 2, cp_col = (lane & 3) << 2;   // ints
        unsigned cp_dst0 = smem_u32(wring) + (unsigned)((cp_row << 6) + cp_col) * 4u;

        auto issue4 = [&](const int* src, int slot) {
            unsigned dst = cp_dst0 + (unsigned)slot * 2048u;
#pragma unroll
            for (int k = 0; k < 4; k++)
                cp16(dst + k * 64u, src + k * 16);
            cp_commit();
        };
        // item decode: it = (b<<10)|(grp<<1)|jsub ; je = (g<<1)|jsub
        auto cpbase = [&](int it) -> const int* {
            int b = it >> 10, grp = (it >> 1) & 511, jsub = it & 1;
            int je = (g << 1) | jsub;
            return adj + ((size_t)((b << 12) + (grp << 3) + cp_row)) * NE
                       + (je << 9) + cp_col;
        };

        // prologue: item0 chunks 0..4 -> slots 0..4
        {
            const int* s0 = cpbase(wslot);
            issue4(s0,       0);
            issue4(s0 + 64,  1);
            issue4(s0 + 128, 2);
            issue4(s0 + 192, 3);
            issue4(s0 + 256, 4);
        }

        ull Sp[4] = {0,0,0,0}, T0p[4] = {0,0,0,0}, T1p[4] = {0,0,0,0}, T2p[4] = {0,0,0,0};

        int it = wslot;
        const int* curSrc = cpbase(it);
        int scur = 0;                                 // slot of current step
        for (int itIdx = 0; itIdx < nItems; itIdx++) {
            bool hn = (itIdx + 1 < nItems);
            int b = it >> 10, grp = (it >> 1) & 511, jsub = it & 1;
            int je = (g << 1) | jsub;
            int row0 = (grp << 3) + halfr0;
            int nit = it + NWSLOT_G;
            const int* nextSrc = hn ? cpbase(nit) : curSrc;

            // per-item row constants
            ull Ca2[4], Cb2[4];
            float W0s[4];
#pragma unroll
            for (int rr = 0; rr < 4; rr++) {
                float z  = __ldg(&g_src[row0 + rr]) + Md;
                float lr = z > 0.f ? z : 0.2f * z;
                float Cc = fmaxf(lr, 9e-15f);
                float ca = expf(z - Cc), cb = expf(0.2f * z - Cc);
                Ca2[rr] = pack2(ca, ca);
                Cb2[rr] = pack2(cb, cb);
                W0s[rr] = expf(9e-15f - Cc);
            }

            int jg0 = (jsub << 9) + (lsub << 2);      // local table offset
            const float* tq  = sq  + jg0;
            const float* tq2 = sq2 + jg0;
            const float* th0 = sh0 + jg0;
            const float* th1 = sh1 + jg0;
            const float* th2 = sh2 + jg0;

#pragma unroll
            for (int c = 0; c < 8; c++) {
                // independent table loads BEFORE the wait (constant offsets)
                double2 Qd  = *(const double2*)(tq  + c * 64);
                double2 Q2d = *(const double2*)(tq2 + c * 64);
                double2 H0d = *(const double2*)(th0 + c * 64);
                double2 H1d = *(const double2*)(th1 + c * 64);
                double2 H2d = *(const double2*)(th2 + c * 64);
                ull qlo  = __double_as_longlong(Qd.x),  qhi  = __double_as_longlong(Qd.y);
                ull q2lo = __double_as_longlong(Q2d.x), q2hi = __double_as_longlong(Q2d.y);
                ull h0lo = __double_as_longlong(H0d.x), h0hi = __double_as_longlong(H0d.y);
                ull h1lo = __double_as_longlong(H1d.x), h1hi = __double_as_longlong(H1d.y);
                ull h2lo = __double_as_longlong(H2d.x), h2hi = __double_as_longlong(H2d.y);

                // prefetch step+5 into slot (scur+5)%6
                int slot_i = scur >= 1 ? scur - 1 : 5;
                if (c < 3) {
                    issue4(curSrc + (c + 5) * 64, slot_i);
                    cp_wait5();
                } else if (hn) {
                    issue4(nextSrc + (c - 3) * 64, slot_i);
                    cp_wait5();
                } else {
                    cp_wait0();
                }
                __syncwarp();

                const int* st = wring + scur * 512;
#pragma unroll
                for (int rr = 0; rr < 4; rr++) {
                    int4 aa = *(const int4*)(st + ((halfr0 + rr) << 6) + (lsub << 2));
                    {
                        ull t1 = mul2(Ca2[rr], qlo), t2 = mul2(Cb2[rr], q2lo);
                        float m0, m1, n0, n1;
                        unpack2(m0, m1, t1); unpack2(n0, n1, t2);
                        float w0 = (aa.x > 0) ? fmaxf(m0, n0) : W0s[rr];
                        float w1 = (aa.y > 0) ? fmaxf(m1, n1) : W0s[rr];
                        ull wp = pack2(w0, w1);
                        ADD_X2(Sp[rr], Sp[rr], wp);
                        FMA_X2(T0p[rr], wp, h0lo, T0p[rr]);
                        FMA_X2(T1p[rr], wp, h1lo, T1p[rr]);
                        FMA_X2(T2p[rr], wp, h2lo, T2p[rr]);
                    }
                    {
                        ull t1 = mul2(Ca2[rr], qhi), t2 = mul2(Cb2[rr], q2hi);
                        float m0, m1, n0, n1;
                        unpack2(m0, m1, t1); unpack2(n0, n1, t2);
                        float w0 = (aa.z > 0) ? fmaxf(m0, n0) : W0s[rr];
                        float w1 = (aa.w > 0) ? fmaxf(m1, n1) : W0s[rr];
                        ull wp = pack2(w0, w1);
                        ADD_X2(Sp[rr], Sp[rr], wp);
                        FMA_X2(T0p[rr], wp, h0hi, T0p[rr]);
                        FMA_X2(T1p[rr], wp, h1hi, T1p[rr]);
                        FMA_X2(T2p[rr], wp, h2hi, T2p[rr]);
                    }
                }
                scur = scur < 5 ? scur + 1 : 0;
            }

            // per-item epilogue: fold packed pairs, half-warp reduce, store
            {
                float S[4], T0[4], T1[4], T2[4];
#pragma unroll
                for (int rr = 0; rr < 4; rr++) {
                    float lo, hi;
                    unpack2(lo, hi, Sp[rr]);  S[rr]  = lo + hi;
                    unpack2(lo, hi, T0p[rr]); T0[rr] = lo + hi;
                    unpack2(lo, hi, T1p[rr]); T1[rr] = lo + hi;
                    unpack2(lo, hi, T2p[rr]); T2[rr] = lo + hi;
                    Sp[rr] = 0ull; T0p[rr] = 0ull; T1p[rr] = 0ull; T2p[rr] = 0ull;
                }
#pragma unroll
                for (int o = 8; o > 0; o >>= 1) {
#pragma unroll
                    for (int rr = 0; rr < 4; rr++) {
                        S[rr]  += __shfl_xor_sync(0xffffffffu, S[rr],  o);
                        T0[rr] += __shfl_xor_sync(0xffffffffu, T0[rr], o);
                        T1[rr] += __shfl_xor_sync(0xffffffffu, T1[rr], o);
                        T2[rr] += __shfl_xor_sync(0xffffffffu, T2[rr], o);
                    }
                }
                if (lsub == 0) {
#pragma unroll
                    for (int rr = 0; rr < 4; rr++) {
                        int idx = (b << 12) + row0 + rr;
                        g_pS[je][idx]  = S[rr];
                        g_pT0[je][idx] = T0[rr];
                        g_pT1[je][idx] = T1[rr];
                        g_pT2[je][idx] = T2[rr];
                    }
                }
            }

            it = nit;
            curSrc = nextSrc;
        }

        // ---- FC blocks: stage their w row into OWN (now idle) ring region ----
        // warp s stages w floats [s*768, s*768+768) at ringf[s*WRING_INTS + l].
        if (bid < FCO) {
            const float* wsrc = fcw + (size_t)bid * (NE * 3) + warp * 768 + lane * 4;
            unsigned wdst = smem_u32(ringf + warp * WRING_INTS) + (unsigned)(lane * 16);
#pragma unroll
            for (int i = 0; i < 6; i++)
                cp16(wdst + (unsigned)i * 512u, wsrc + i * 128);
            cp_commit();
        }
    }
    gsync();

    // ---------------- Phase 2 window ----------------------------------------
    // blocks 100-131: combine + ELU.  FC blocks (0-99): pull w smem -> regs.
    float4 wv[6];
    if (bid < FCO) {
        cp_wait0();
        __syncthreads();   // cross-warp smem visibility of staged w
#pragma unroll
        for (int i = 0; i < 6; i++) {
            // w float index f -> ringf[(f/768)*WRING_INTS + f%768]
            int f = i * 2048 + tid * 4;
            int s = f / 768;
            int l = f - s * 768;
            wv[i] = *(const float4*)(ringf + s * WRING_INTS + l);
        }
    } else if (bid < 132) {
        int t = (bid - 100) * NTHR + tid;   // 0..16383 exactly
        float S = 0.f, v0 = 0.f, v1 = 0.f, v2 = 0.f;
#pragma unroll
        for (int e = 0; e < 8; e++) {
            S  += g_pS[e][t];
            v0 += g_pT0[e][t];
            v1 += g_pT1[e][t];
            v2 += g_pT2[e][t];
        }
        float inv = 1.f / S;
        v0 *= inv; v1 *= inv; v2 *= inv;
        v0 = v0 > 0.f ? v0 : expm1f(v0);
        v1 = v1 > 0.f ? v1 : expm1f(v1);
        v2 = v2 > 0.f ? v2 : expm1f(v2);
        g_x[t * 3 + 0] = v0;
        g_x[t * 3 + 1] = v1;
        g_x[t * 3 + 2] = v2;
    }
    gsync();

    // ---------------- Phase 3: FC (blocks 0-99, one k each) -----------------
    if (bid < FCO) {
        int k = bid;
        float acc[NB] = {0.f, 0.f, 0.f, 0.f};
#pragma unroll
        for (int i = 0; i < 6; i++) {
            int n = i * 2048 + tid * 4;
#pragma unroll
            for (int b = 0; b < NB; b++) {
                float4 xv = *(const float4*)(g_x + b * NE * 3 + n);
                acc[b] = fmaf(wv[i].x, xv.x, fmaf(wv[i].y, xv.y,
                         fmaf(wv[i].z, xv.z, fmaf(wv[i].w, xv.w, acc[b]))));
            }
        }
#pragma unroll
        for (int o = 16; o > 0; o >>= 1)
#pragma unroll
            for (int b = 0; b < NB; b++)
                acc[b] += __shfl_xor_sync(0xffffffffu, acc[b], o);

        float* sred = (float*)ring;   // reuse ring smem (w already in regs)
        __syncthreads();
        if (lane == 0) {
#pragma unroll
            for (int b = 0; b < NB; b++) sred[warp * NB + b] = acc[b];
        }
        __syncthreads();
        if (tid < NB) {
            float s = __ldg(fcb + k);
#pragma unroll
            for (int ww = 0; ww < NWARP; ww++) s += sred[ww * NB + tid];
            out[tid * FCO + k] = s;
        }
    }
}

// ---------------------------------------------------------------------------
extern "C" void kernel_launch(void* const* d_in, const int* in_sizes, int n_in,
                              void* d_out, int out_size)
{
    const int*   adj = (const int*)d_in[0];
    const float* emb = (const float*)d_in[1];
    const float* W   = (const float*)d_in[2];
    const float* av  = (const float*)d_in[3];
    const float* fcw = (const float*)d_in[4];
    const float* fcb = (const float*)d_in[5];
    float* out = (float*)d_out;

    cudaFuncSetAttribute(k_all, cudaFuncAttributeMaxDynamicSharedMemorySize,
                         SMEM_BYTES);

    k_all<<<GRID, NTHR, SMEM_BYTES>>>(adj, emb, W, av, fcw, fcb, out);
}